// round 16
// baseline (speedup 1.0000x reference)
#include <cuda_runtime.h>
#include <math.h>
#include <stdint.h>

#define BB 64
#define TT_ 1024
#define FF 512
#define II 256
#define SS 128
#define MM 64
#define NPROJ 384
#define STT 16
#define NC 8
#define CHT (TT_ / NC)          // 128 timesteps per chunk

// ---------------- scratch (static device globals; no allocation) ----------------
__device__ float g_proj[(size_t)BB * TT_ * NPROJ];   // tanh(inputs@W_in+b)  (B*T, 384)
__device__ float g_CG [(size_t)BB * TT_ * SS];       // C (then *= sigmoid(softmax(gate)))
__device__ float g_wns[(size_t)BB * TT_ * SS];       // sensory num + per-k num consts
__device__ float g_wds[(size_t)BB * TT_ * SS];       // sensory den + per-k den consts
__device__ float g_RA1[SS * SS], g_RA2[SS * SS];     // recurrent 0.5*sigma / -0.5*sigma*mu, [k][j]
__device__ float g_RWN[SS * SS];                     // 0.5*w*mask*erev, [j][k]
__device__ float g_SA1[II * SS], g_SA2[II * SS], g_SWN[II * SS];   // sensory, [i][k]
__device__ float g_cmt[SS], g_nadd[SS], g_dadd[SS];

// pipeline flags (reset each launch by reset_kernel)
__device__ int g_prep_ready;                          // monotonic: chunks of wns/wds ready
__device__ int g_scan_ctr[NC];                        // per-chunk scan-CTA completion count

__device__ __forceinline__ float tanh_fast(float x) {
    float r;
    asm("tanh.approx.f32 %0, %1;" : "=f"(r) : "f"(x));
    return r;
}

// ---------------- flag helpers ----------------
__global__ void reset_kernel()
{
    if (threadIdx.x == 0) g_prep_ready = 0;
    if (threadIdx.x < NC) g_scan_ctr[threadIdx.x] = 0;
}

__global__ void set_kernel(int c)
{
    if (threadIdx.x == 0) {
        int* p = &g_prep_ready;
        asm volatile("st.release.gpu.global.s32 [%0], %1;" :: "l"(p), "r"(c + 1) : "memory");
    }
}

// spin until all BB scan CTAs finished chunk c (runs on s1, 1 warp)
__global__ void gate_kernel(int c)
{
    if (threadIdx.x == 0) {
        int* p = &g_scan_ctr[c];
        int v;
        do {
            asm volatile("ld.acquire.gpu.global.s32 %0, [%1];" : "=r"(v) : "l"(p) : "memory");
            if (v >= BB) break;
            __nanosleep(200);
        } while (true);
    }
}

// ---------------- param preprocessing ----------------
// sigmoid((v-mu)*sigma) = 0.5 + 0.5*tanh(0.5*sigma*(v-mu))
__global__ void prep_kernel(const float* __restrict__ w, const float* __restrict__ sigma,
                            const float* __restrict__ mu, const float* __restrict__ erev,
                            const float* __restrict__ mask,
                            const float* __restrict__ sw, const float* __restrict__ ssig,
                            const float* __restrict__ smu, const float* __restrict__ serev,
                            const float* __restrict__ smask,
                            const float* __restrict__ gleak, const float* __restrict__ vleak,
                            const float* __restrict__ cm)
{
    int idx = blockIdx.x * blockDim.x + threadIdx.x;
    if (idx < SS * SS) {
        int j = idx / SS, k = idx % SS;
        float sg = sigma[idx], m = mu[idx];
        g_RA1[k * SS + j] = 0.5f * sg;
        g_RA2[k * SS + j] = -0.5f * sg * m;
        g_RWN[idx] = 0.5f * w[idx] * mask[idx] * erev[idx];   // [j][k], halved, signed
    }
    int i2 = idx - SS * SS;
    if (i2 >= 0 && i2 < II * SS) {
        float sg = ssig[i2], m = smu[i2];
        g_SA1[i2] = 0.5f * sg;
        g_SA2[i2] = -0.5f * sg * m;
        g_SWN[i2] = 0.5f * sw[i2] * smask[i2] * serev[i2];
    }
    int i3 = idx - SS * SS - II * SS;
    if (i3 >= 0 && i3 < SS) {
        float c = cm[i3] * 6.0f;               // cm / (ELAPSED/ODE_UNFOLDS)
        g_cmt[i3]  = c;
        g_nadd[i3] = gleak[i3] * vleak[i3];
        g_dadd[i3] = c + gleak[i3] + 1e-8f;
    }
}

// fold 0.5*sum(w), 0.5*sum(|w|) (recurrent + sensory) into the additive constants
__global__ void prep2_kernel()
{
    int k = threadIdx.x;
    float ns = 0.f, ds = 0.f;
    for (int j = 0; j < SS; j++) {
        float x = g_RWN[j * SS + k];
        ns += x; ds += fabsf(x);
    }
    for (int i = 0; i < II; i++) {
        float x = g_SWN[i * SS + k];
        ns += x; ds += fabsf(x);
    }
    g_nadd[k] += ns;
    g_dadd[k] += ds;
}

// ---------------- generic tiled SIMT GEMM (BM=128, BN=64, BK=16, 256 thr) ----------------
// t0 < 0: rows = blockIdx.y*128 (full).  t0 >= 0: rows = blockIdx.y*TT_ + t0 (chunked).
template <int ACT>
__global__ void __launch_bounds__(256) gemm_kernel(const float* __restrict__ A, int lda,
                                                   const float* __restrict__ B, int ldb,
                                                   const float* __restrict__ bias,
                                                   float* __restrict__ C, int ldc, int K,
                                                   int t0)
{
    __shared__ float As[16][128];
    __shared__ float Bs[16][64];
    int tid = threadIdx.x;
    int bm = (t0 < 0) ? blockIdx.y * 128 : (blockIdx.y * TT_ + t0);
    int bn = blockIdx.x * 64;
    int tx = tid & 15, ty = tid >> 4;
    int a_m = tid >> 2;
    int a_k = (tid & 3) * 4;
    int b_k = tid >> 4;
    int b_n = (tid & 15) * 4;

    float acc[8][4];
#pragma unroll
    for (int i = 0; i < 8; i++)
#pragma unroll
        for (int j = 0; j < 4; j++) acc[i][j] = 0.f;

    for (int k0 = 0; k0 < K; k0 += 16) {
#pragma unroll
        for (int i = 0; i < 2; i++) {
            float4 va = *(const float4*)(A + (size_t)(bm + a_m + i * 64) * lda + k0 + a_k);
            As[a_k + 0][a_m + i * 64] = va.x;
            As[a_k + 1][a_m + i * 64] = va.y;
            As[a_k + 2][a_m + i * 64] = va.z;
            As[a_k + 3][a_m + i * 64] = va.w;
        }
        *(float4*)(&Bs[b_k][b_n]) = *(const float4*)(B + (size_t)(k0 + b_k) * ldb + bn + b_n);
        __syncthreads();
#pragma unroll
        for (int kk = 0; kk < 16; kk++) {
            float a[8], bv[4];
#pragma unroll
            for (int i = 0; i < 8; i++) a[i] = As[kk][ty * 8 + i];
#pragma unroll
            for (int j = 0; j < 4; j++) bv[j] = Bs[kk][tx * 4 + j];
#pragma unroll
            for (int i = 0; i < 8; i++)
#pragma unroll
                for (int j = 0; j < 4; j++) acc[i][j] = fmaf(a[i], bv[j], acc[i][j]);
        }
        __syncthreads();
    }
    float4 bb = *(const float4*)(bias + bn + tx * 4);
    float bv4[4] = {bb.x, bb.y, bb.z, bb.w};
#pragma unroll
    for (int i = 0; i < 8; i++) {
        int m = bm + ty * 8 + i;
        float4 o;
        float v0 = acc[i][0] + bv4[0], v1 = acc[i][1] + bv4[1];
        float v2 = acc[i][2] + bv4[2], v3 = acc[i][3] + bv4[3];
        if (ACT == 1) { v0 = tanhf(v0); v1 = tanhf(v1); v2 = tanhf(v2); v3 = tanhf(v3); }
        o.x = v0; o.y = v1; o.z = v2; o.w = v3;
        *(float4*)(C + (size_t)m * ldc + bn + tx * 4) = o;
    }
}

// ---------------- softmax over T (axis=1) + fold sigmoid into CG ----------------
__global__ void __launch_bounds__(256) softmax_cg_kernel()
{
    int b = blockIdx.y;
    int s0 = blockIdx.x * 32;
    int s = threadIdx.x & 31;
    int g = threadIdx.x >> 5;          // 0..7
    __shared__ float red[8][32];
    __shared__ float rsh[32];

    const float* gp = g_proj + (size_t)b * TT_ * NPROJ + II + s0 + s;
    float sum = 0.f;
#pragma unroll 4
    for (int t = g * 128; t < g * 128 + 128; t++)
        sum += __expf(gp[(size_t)t * NPROJ]);
    red[g][s] = sum;
    __syncthreads();
    if (g == 0) {
        float tot = 0.f;
#pragma unroll
        for (int i = 0; i < 8; i++) tot += red[i][s];
        rsh[s] = __fdividef(1.f, tot);
    }
    __syncthreads();
    float rs = rsh[s];
    float* cg = g_CG + (size_t)b * TT_ * SS + s0 + s;
#pragma unroll 4
    for (int t = g * 128; t < g * 128 + 128; t++) {
        float p = __expf(gp[(size_t)t * NPROJ]) * rs;
        float sg = __fdividef(1.f, 1.f + __expf(-p));
        cg[(size_t)t * SS] *= sg;
    }
}

// ---------------- sensory precompute (chunked): per (b,t,k) w_num_s/w_den_s ----------------
__global__ void __launch_bounds__(128) sensory_kernel(int t0)
{
    int blk = blockIdx.x;
    int b = blk / (CHT / STT);
    int cc = blk % (CHT / STT);
    __shared__ float sh[STT][II];
    int tid = threadIdx.x;
    size_t rowbase = (size_t)b * TT_ + t0 + cc * STT;
    for (int idx = tid; idx < STT * II; idx += 128) {
        int tt = idx >> 8, i = idx & 255;
        sh[tt][i] = g_proj[(rowbase + tt) * NPROJ + i];
    }
    __syncthreads();
    int k = tid;
    float num[STT], den[STT];
#pragma unroll
    for (int tt = 0; tt < STT; tt++) { num[tt] = 0.f; den[tt] = 0.f; }
    for (int i = 0; i < II; i++) {
        float a1 = g_SA1[i * SS + k];
        float a2 = g_SA2[i * SS + k];
        float wv = g_SWN[i * SS + k];
        float aw = fabsf(wv);
#pragma unroll
        for (int tt = 0; tt < STT; tt++) {
            float th = tanh_fast(fmaf(sh[tt][i], a1, a2));
            num[tt] = fmaf(wv, th, num[tt]);
            den[tt] = fmaf(aw, th, den[tt]);
        }
    }
    float na = g_nadd[k], da = g_dadd[k];
#pragma unroll
    for (int tt = 0; tt < STT; tt++) {
        size_t row = rowbase + tt;
        g_wns[row * SS + k] = num[tt] + na;
        g_wds[row * SS + k] = den[tt] + da;
    }
}

// ---------------- sequential ODE scan v7: persistent, 256 thr, ONE barrier/unfold ----------
// Lane pair owns one k: k = warp*16 + (lane>>1), h = lane&1 takes j in [h*64, h*64+64).
//  - wa1/wa2 coefficient halves in REGISTERS (128 regs/thread; 256 thr -> fits)
//  - weights in smem layout [q][h*144 + k]: bank = (16h + k) & 31 -> 32 distinct banks
//    across the warp (h-stride 144 = 16 mod 32), conflict-free scalar LDS
//  - v double-buffered, read as float4 (2 addresses/warp, broadcast)
//  - k-reduction: single shfl.bfly(1) pair; both lanes update vk redundantly;
//    h==0 writes sv[p^1]; ONE __syncthreads per unfold
//  - persistent over all NC chunks (flags protocol identical to round 15)
// LDS/warp/unfold ~ 64(w)+32(v) wavefronts * 8 warps ~ 770 cyc < MUFU 1024 -> MUFU-bound.
#define WQSTR 288                       // 2*144 floats per q row
#define SCAN_SMEM ((64 * WQSTR + 2 * SS) * 4)

__global__ void __launch_bounds__(256, 1)
scan_kernel(const float* __restrict__ v0,
            float* __restrict__ fused_out,
            float* __restrict__ vfinal)
{
    extern __shared__ float smem[];
    float* swt = smem;                   // [64][2*144]
    float* svb[2];
    svb[0] = swt + 64 * WQSTR;           // 128, 16B aligned
    svb[1] = svb[0] + SS;

    int b = blockIdx.x;
    int tid = threadIdx.x;
    int w = tid >> 5;
    int l = tid & 31;
    int k = w * 16 + (l >> 1);           // 0..127
    int h = l & 1;
    bool leader = (h == 0);

    // weights into smem: g_RWN[j][k] -> swt[(j&63)*288 + (j>>6)*144 + k]
    for (int idx = tid; idx < SS * SS; idx += 256) {
        int j = idx >> 7, kk = idx & 127;
        swt[(j & 63) * WQSTR + (j >> 6) * 144 + kk] = g_RWN[idx];
    }
    // coefficient registers: j = h*64 + q
    float wa1[64], wa2[64];
#pragma unroll
    for (int q = 0; q < 64; q++) {
        wa1[q] = g_RA1[k * SS + h * 64 + q];
        wa2[q] = g_RA2[k * SS + h * 64 + q];
    }

    if (tid < SS) svb[0][tid] = v0[b * SS + tid];
    float cmt = g_cmt[k];
    float vk = v0[b * SS + k];
    __syncthreads();

    int hk = h * 144 + k;
    size_t row = (size_t)b * TT_;
    int p = 0;

    for (int c = 0; c < NC; c++) {
        // wait for this chunk's wns/wds (usually already set -> single acquire load)
        if (tid == 0) {
            int* pr = &g_prep_ready;
            int v;
            do {
                asm volatile("ld.acquire.gpu.global.s32 %0, [%1];" : "=r"(v) : "l"(pr) : "memory");
                if (v >= c + 1) break;
                __nanosleep(200);
            } while (true);
        }
        __syncthreads();

#pragma unroll 1
        for (int t = 0; t < CHT; t++, row++) {
            float wns = g_wns[row * SS + k];     // lane pair loads same addr (broadcast)
            float wds = g_wds[row * SS + k];
#pragma unroll 1
            for (int u = 0; u < 6; u++) {
                const float4* sv4 = (const float4*)(svb[p] + h * 64);
                float num = 0.f, den = 0.f;
#pragma unroll
                for (int q4 = 0; q4 < 16; q4++) {
                    float4 vv = sv4[q4];                       // 2 addrs/warp, broadcast
                    int q = q4 * 4;
                    float w0 = swt[(q + 0) * WQSTR + hk];      // conflict-free LDS.32
                    float w1 = swt[(q + 1) * WQSTR + hk];
                    float w2 = swt[(q + 2) * WQSTR + hk];
                    float w3 = swt[(q + 3) * WQSTR + hk];
                    float t0h = tanh_fast(fmaf(vv.x, wa1[q + 0], wa2[q + 0]));
                    float t1h = tanh_fast(fmaf(vv.y, wa1[q + 1], wa2[q + 1]));
                    float t2h = tanh_fast(fmaf(vv.z, wa1[q + 2], wa2[q + 2]));
                    float t3h = tanh_fast(fmaf(vv.w, wa1[q + 3], wa2[q + 3]));
                    num = fmaf(w0, t0h, num); den = fmaf(fabsf(w0), t0h, den);
                    num = fmaf(w1, t1h, num); den = fmaf(fabsf(w1), t1h, den);
                    num = fmaf(w2, t2h, num); den = fmaf(fabsf(w2), t2h, den);
                    num = fmaf(w3, t3h, num); den = fmaf(fabsf(w3), t3h, den);
                }
                // combine the two j-halves of this k (lanes l, l^1)
                num += __shfl_xor_sync(0xffffffffu, num, 1);
                den += __shfl_xor_sync(0xffffffffu, den, 1);
                float nt = fmaf(cmt, vk, wns + num);
                vk = nt * __fdividef(1.f, wds + den);
                if (leader) svb[p ^ 1][k] = vk;
                __syncthreads();                               // single barrier per unfold
                p ^= 1;
            }
            if (leader) fused_out[row * SS + k] = vk;          // raw v; CG applied in post
        }

        // publish chunk completion (stores -> fence -> counter)
        __threadfence();
        __syncthreads();
        if (tid == 0) atomicAdd(&g_scan_ctr[c], 1);
    }
    if (leader) vfinal[b * SS + k] = vk;
}

// ---------------- post (chunked): fused = v * CG for chunk at t0 ----------------
__global__ void __launch_bounds__(256) post_kernel(float* __restrict__ fused, int t0)
{
    int b = blockIdx.y;
    size_t base = ((size_t)b * TT_ + t0) * SS / 4;
    size_t i = base + blockIdx.x * 256 + threadIdx.x;
    float4 f = ((float4*)fused)[i];
    float4 c = ((const float4*)g_CG)[i];
    f.x *= c.x; f.y *= c.y; f.z *= c.z; f.w *= c.w;
    ((float4*)fused)[i] = f;
}

// ---------------- streams/events (created at load, before harness checkpoints) ----------------
struct PipeRes {
    cudaStream_t s1;
    cudaEvent_t evFork, evJoin, evSens0;
    PipeRes() {
        cudaStreamCreateWithFlags(&s1, cudaStreamNonBlocking);
        cudaEventCreateWithFlags(&evFork, cudaEventDisableTiming);
        cudaEventCreateWithFlags(&evJoin, cudaEventDisableTiming);
        cudaEventCreateWithFlags(&evSens0, cudaEventDisableTiming);
    }
};
static PipeRes g_pipe;

// ---------------- launch ----------------
extern "C" void kernel_launch(void* const* d_in, const int* in_sizes, int n_in,
                              void* d_out, int out_size)
{
    const float* inputs    = (const float*)d_in[0];
    const float* ode_state = (const float*)d_in[1];
    const float* W_in      = (const float*)d_in[2];
    const float* b_in      = (const float*)d_in[3];
    const float* W_c       = (const float*)d_in[4];
    const float* b_c       = (const float*)d_in[5];
    const float* W_out     = (const float*)d_in[6];
    const float* b_out     = (const float*)d_in[7];
    const float* gleak     = (const float*)d_in[8];
    const float* vleak     = (const float*)d_in[9];
    const float* cm        = (const float*)d_in[10];
    const float* w         = (const float*)d_in[11];
    const float* sigma     = (const float*)d_in[12];
    const float* mu        = (const float*)d_in[13];
    const float* sw        = (const float*)d_in[14];
    const float* ssig      = (const float*)d_in[15];
    const float* smu       = (const float*)d_in[16];
    const float* erev      = (const float*)d_in[17];
    const float* serev     = (const float*)d_in[18];
    const float* mask      = (const float*)d_in[19];
    const float* smask     = (const float*)d_in[20];

    float* out      = (float*)d_out;                          // (B,T,M)
    float* vfinal   = out + (size_t)BB * TT_ * MM;            // (B,S)
    float* fusedout = vfinal + (size_t)BB * SS;               // (B,T,S)

    float *p_proj, *p_cg;
    cudaGetSymbolAddress((void**)&p_proj, g_proj);
    cudaGetSymbolAddress((void**)&p_cg, g_CG);

    cudaFuncSetAttribute(scan_kernel, cudaFuncAttributeMaxDynamicSharedMemorySize, SCAN_SMEM);

    cudaStream_t s0 = 0, s1 = g_pipe.s1;

    // ---- serial prologue on s0 ----
    reset_kernel<<<1, 32, 0, s0>>>();
    int prep_n = SS * SS + II * SS + SS;
    prep_kernel<<<(prep_n + 255) / 256, 256, 0, s0>>>(w, sigma, mu, erev, mask,
                                                      sw, ssig, smu, serev, smask,
                                                      gleak, vleak, cm);
    prep2_kernel<<<1, 128, 0, s0>>>();
    cudaEventRecord(g_pipe.evFork, s0);
    cudaStreamWaitEvent(s1, g_pipe.evFork, 0);

    // ---- preprocessing pipeline on s1 (chunked over T), flags after each chunk ----
    for (int c = 0; c < NC; c++) {
        int t0 = c * CHT;
        gemm_kernel<1><<<dim3(NPROJ / 64, BB), 256, 0, s1>>>(
            inputs, FF, W_in, NPROJ, b_in, p_proj, NPROJ, FF, t0);
        gemm_kernel<0><<<dim3(SS / 64, BB), 256, 0, s1>>>(
            p_proj, NPROJ, W_c, SS, b_c, p_cg, SS, II, t0);
        sensory_kernel<<<BB * (CHT / STT), 128, 0, s1>>>(t0);
        set_kernel<<<1, 32, 0, s1>>>(c);
        if (c == 0) cudaEventRecord(g_pipe.evSens0, s1);
    }
    // softmax over full T, folds sigmoid into CG in place
    softmax_cg_kernel<<<dim3(4, BB), 256, 0, s1>>>();

    // ---- persistent scan on s0 (starts after chunk 0 so chunk-0 preproc gets full chip)
    cudaStreamWaitEvent(s0, g_pipe.evSens0, 0);
    scan_kernel<<<BB, 256, SCAN_SMEM, s0>>>(ode_state, fusedout, vfinal);

    // ---- epilogue on s1, chunked, gated on scan progress via device flags ----
    for (int c = 0; c < NC; c++) {
        int t0 = c * CHT;
        gate_kernel<<<1, 32, 0, s1>>>(c);
        post_kernel<<<dim3(CHT * SS / (4 * 256), BB), 256, 0, s1>>>(fusedout, t0);
        gemm_kernel<0><<<dim3(MM / 64, BB), 256, 0, s1>>>(
            fusedout, SS, W_out, MM, b_out, out, MM, SS, t0);
    }
    // join: s0 (the measured stream) waits for the s1 epilogue
    cudaEventRecord(g_pipe.evJoin, s1);
    cudaStreamWaitEvent(s0, g_pipe.evJoin, 0);
}

// round 17
// speedup vs baseline: 1.5194x; 1.5194x over previous
#include <cuda_runtime.h>
#include <math.h>
#include <stdint.h>

#define BB 64
#define TT_ 1024
#define FF 512
#define II 256
#define SS 128
#define MM 64
#define NPROJ 384
#define STT 16
#define NC 16
#define CHT (TT_ / NC)          // 64 timesteps per chunk

// ---------------- scratch (static device globals; no allocation) ----------------
__device__ float g_proj[(size_t)BB * TT_ * NPROJ];   // tanh(inputs@W_in+b)  (B*T, 384)
__device__ float g_CG [(size_t)BB * TT_ * SS];       // C (then *= sigmoid(softmax(gate)))
__device__ float g_wns[(size_t)BB * TT_ * SS];       // sensory num + per-k num consts
__device__ float g_wds[(size_t)BB * TT_ * SS];       // sensory den + per-k den consts
__device__ float g_RA1[SS * SS], g_RA2[SS * SS];     // recurrent 0.5*sigma / -0.5*sigma*mu, [k][j]
__device__ float g_RWN[SS * SS];                     // 0.5*w*mask*erev, [j][k]
__device__ float g_SA1[II * SS], g_SA2[II * SS], g_SWN[II * SS];   // sensory, [i][k]
__device__ float g_cmt[SS], g_nadd[SS], g_dadd[SS];

// pipeline flags (reset each launch by reset_kernel)
__device__ int g_prep_ready;                          // monotonic: chunks of wns/wds ready
__device__ int g_scan_ctr[NC];                        // per-chunk scan-CTA completion count

__device__ __forceinline__ float tanh_fast(float x) {
    float r;
    asm("tanh.approx.f32 %0, %1;" : "=f"(r) : "f"(x));
    return r;
}

// ---------------- flag helpers ----------------
__global__ void reset_kernel()
{
    if (threadIdx.x == 0) g_prep_ready = 0;
    if (threadIdx.x < NC) g_scan_ctr[threadIdx.x] = 0;
}

__global__ void set_kernel(int c)
{
    if (threadIdx.x == 0) {
        int* p = &g_prep_ready;
        asm volatile("st.release.gpu.global.s32 [%0], %1;" :: "l"(p), "r"(c + 1) : "memory");
    }
}

// spin until all BB scan CTAs finished chunk c (runs on s1, 1 warp)
__global__ void gate_kernel(int c)
{
    if (threadIdx.x == 0) {
        int* p = &g_scan_ctr[c];
        int v;
        do {
            asm volatile("ld.acquire.gpu.global.s32 %0, [%1];" : "=r"(v) : "l"(p) : "memory");
            if (v >= BB) break;
            __nanosleep(200);
        } while (true);
    }
}

// ---------------- param preprocessing ----------------
// sigmoid((v-mu)*sigma) = 0.5 + 0.5*tanh(0.5*sigma*(v-mu))
__global__ void prep_kernel(const float* __restrict__ w, const float* __restrict__ sigma,
                            const float* __restrict__ mu, const float* __restrict__ erev,
                            const float* __restrict__ mask,
                            const float* __restrict__ sw, const float* __restrict__ ssig,
                            const float* __restrict__ smu, const float* __restrict__ serev,
                            const float* __restrict__ smask,
                            const float* __restrict__ gleak, const float* __restrict__ vleak,
                            const float* __restrict__ cm)
{
    int idx = blockIdx.x * blockDim.x + threadIdx.x;
    if (idx < SS * SS) {
        int j = idx / SS, k = idx % SS;
        float sg = sigma[idx], m = mu[idx];
        g_RA1[k * SS + j] = 0.5f * sg;
        g_RA2[k * SS + j] = -0.5f * sg * m;
        g_RWN[idx] = 0.5f * w[idx] * mask[idx] * erev[idx];   // [j][k], halved, signed
    }
    int i2 = idx - SS * SS;
    if (i2 >= 0 && i2 < II * SS) {
        float sg = ssig[i2], m = smu[i2];
        g_SA1[i2] = 0.5f * sg;
        g_SA2[i2] = -0.5f * sg * m;
        g_SWN[i2] = 0.5f * sw[i2] * smask[i2] * serev[i2];
    }
    int i3 = idx - SS * SS - II * SS;
    if (i3 >= 0 && i3 < SS) {
        float c = cm[i3] * 6.0f;               // cm / (ELAPSED/ODE_UNFOLDS)
        g_cmt[i3]  = c;
        g_nadd[i3] = gleak[i3] * vleak[i3];
        g_dadd[i3] = c + gleak[i3] + 1e-8f;
    }
}

// fold 0.5*sum(w), 0.5*sum(|w|) (recurrent + sensory) into the additive constants
__global__ void prep2_kernel()
{
    int k = threadIdx.x;
    float ns = 0.f, ds = 0.f;
    for (int j = 0; j < SS; j++) {
        float x = g_RWN[j * SS + k];
        ns += x; ds += fabsf(x);
    }
    for (int i = 0; i < II; i++) {
        float x = g_SWN[i * SS + k];
        ns += x; ds += fabsf(x);
    }
    g_nadd[k] += ns;
    g_dadd[k] += ds;
}

// ---------------- generic tiled SIMT GEMM (BM=128, BN=64, BK=16, 256 thr) ----------------
// t0 < 0: rows = blockIdx.y*128 (full).  t0 >= 0: rows = blockIdx.y*TT_ + t0, BM=CHT rows.
// For chunked use CHT=64 rows per batch: grid.y = BB, block handles 128 rows only when
// t0<0; chunked path uses BM=64 (half tile) -> handled by M_ROWS template param.
template <int ACT, int BM>
__global__ void __launch_bounds__(256) gemm_kernel(const float* __restrict__ A, int lda,
                                                   const float* __restrict__ B, int ldb,
                                                   const float* __restrict__ bias,
                                                   float* __restrict__ C, int ldc, int K,
                                                   int t0)
{
    __shared__ float As[16][128];
    __shared__ float Bs[16][64];
    int tid = threadIdx.x;
    int bm = (t0 < 0) ? blockIdx.y * BM : (blockIdx.y * TT_ + t0);
    int bn = blockIdx.x * 64;
    int tx = tid & 15, ty = tid >> 4;
    int a_m = tid >> 2;            // 0..63
    int a_k = (tid & 3) * 4;
    int b_k = tid >> 4;
    int b_n = (tid & 15) * 4;

    // each thread accumulates RM rows x 4 cols; RM = BM/16
    const int RM = BM / 16;
    float acc[RM][4];
#pragma unroll
    for (int i = 0; i < RM; i++)
#pragma unroll
        for (int j = 0; j < 4; j++) acc[i][j] = 0.f;

    for (int k0 = 0; k0 < K; k0 += 16) {
#pragma unroll
        for (int i = 0; i < BM / 64; i++) {
            float4 va = *(const float4*)(A + (size_t)(bm + a_m + i * 64) * lda + k0 + a_k);
            As[a_k + 0][a_m + i * 64] = va.x;
            As[a_k + 1][a_m + i * 64] = va.y;
            As[a_k + 2][a_m + i * 64] = va.z;
            As[a_k + 3][a_m + i * 64] = va.w;
        }
        *(float4*)(&Bs[b_k][b_n]) = *(const float4*)(B + (size_t)(k0 + b_k) * ldb + bn + b_n);
        __syncthreads();
#pragma unroll
        for (int kk = 0; kk < 16; kk++) {
            float a[RM], bv[4];
#pragma unroll
            for (int i = 0; i < RM; i++) a[i] = As[kk][ty * RM + i];
#pragma unroll
            for (int j = 0; j < 4; j++) bv[j] = Bs[kk][tx * 4 + j];
#pragma unroll
            for (int i = 0; i < RM; i++)
#pragma unroll
                for (int j = 0; j < 4; j++) acc[i][j] = fmaf(a[i], bv[j], acc[i][j]);
        }
        __syncthreads();
    }
    float4 bb = *(const float4*)(bias + bn + tx * 4);
    float bv4[4] = {bb.x, bb.y, bb.z, bb.w};
#pragma unroll
    for (int i = 0; i < RM; i++) {
        int m = bm + ty * RM + i;
        float4 o;
        float v0 = acc[i][0] + bv4[0], v1 = acc[i][1] + bv4[1];
        float v2 = acc[i][2] + bv4[2], v3 = acc[i][3] + bv4[3];
        if (ACT == 1) { v0 = tanhf(v0); v1 = tanhf(v1); v2 = tanhf(v2); v3 = tanhf(v3); }
        o.x = v0; o.y = v1; o.z = v2; o.w = v3;
        *(float4*)(C + (size_t)m * ldc + bn + tx * 4) = o;
    }
}

// ---------------- softmax over T (axis=1) + fold sigmoid into CG ----------------
__global__ void __launch_bounds__(256) softmax_cg_kernel()
{
    int b = blockIdx.y;
    int s0 = blockIdx.x * 32;
    int s = threadIdx.x & 31;
    int g = threadIdx.x >> 5;          // 0..7
    __shared__ float red[8][32];
    __shared__ float rsh[32];

    const float* gp = g_proj + (size_t)b * TT_ * NPROJ + II + s0 + s;
    float sum = 0.f;
#pragma unroll 4
    for (int t = g * 128; t < g * 128 + 128; t++)
        sum += __expf(gp[(size_t)t * NPROJ]);
    red[g][s] = sum;
    __syncthreads();
    if (g == 0) {
        float tot = 0.f;
#pragma unroll
        for (int i = 0; i < 8; i++) tot += red[i][s];
        rsh[s] = __fdividef(1.f, tot);
    }
    __syncthreads();
    float rs = rsh[s];
    float* cg = g_CG + (size_t)b * TT_ * SS + s0 + s;
#pragma unroll 4
    for (int t = g * 128; t < g * 128 + 128; t++) {
        float p = __expf(gp[(size_t)t * NPROJ]) * rs;
        float sg = __fdividef(1.f, 1.f + __expf(-p));
        cg[(size_t)t * SS] *= sg;
    }
}

// ---------------- sensory precompute (chunked): per (b,t,k) w_num_s/w_den_s ----------------
__global__ void __launch_bounds__(128) sensory_kernel(int t0)
{
    int blk = blockIdx.x;
    int b = blk / (CHT / STT);
    int cc = blk % (CHT / STT);
    __shared__ float sh[STT][II];
    int tid = threadIdx.x;
    size_t rowbase = (size_t)b * TT_ + t0 + cc * STT;
    for (int idx = tid; idx < STT * II; idx += 128) {
        int tt = idx >> 8, i = idx & 255;
        sh[tt][i] = g_proj[(rowbase + tt) * NPROJ + i];
    }
    __syncthreads();
    int k = tid;
    float num[STT], den[STT];
#pragma unroll
    for (int tt = 0; tt < STT; tt++) { num[tt] = 0.f; den[tt] = 0.f; }
    for (int i = 0; i < II; i++) {
        float a1 = g_SA1[i * SS + k];
        float a2 = g_SA2[i * SS + k];
        float wv = g_SWN[i * SS + k];
        float aw = fabsf(wv);
#pragma unroll
        for (int tt = 0; tt < STT; tt++) {
            float th = tanh_fast(fmaf(sh[tt][i], a1, a2));
            num[tt] = fmaf(wv, th, num[tt]);
            den[tt] = fmaf(aw, th, den[tt]);
        }
    }
    float na = g_nadd[k], da = g_dadd[k];
#pragma unroll
    for (int tt = 0; tt < STT; tt++) {
        size_t row = rowbase + tt;
        g_wns[row * SS + k] = num[tt] + na;
        g_wds[row * SS + k] = den[tt] + da;
    }
}

// ---------------- sequential ODE scan: PERSISTENT, round-15 inner loop (proven) ----------
// 512 threads, k = tid&127, h = tid>>7 (j-slice of 32). Weights in smem [j][k],
// coefficient slices in registers, smem partials, leader update, 2 bars/unfold,
// float4 sv reads. Flags protocol: g_prep_ready gates chunk entry (NC=16 now),
// per-chunk counters release the s1 epilogue.
#define SCAN_SMEM ((SS * SS + SS + 2 * 4 * SS) * 4)

__global__ void __launch_bounds__(512, 1)
scan_kernel(const float* __restrict__ v0,
            float* __restrict__ fused_out,
            float* __restrict__ vfinal)
{
    extern __shared__ float smem[];
    float* swt  = smem;                  // [j][k] 128x128 (64KB, 16B-aligned)
    float* sv   = swt + SS * SS;         // 128 (16B-aligned)
    float* snum = sv + SS;               // 4x128
    float* sden = snum + 4 * SS;         // 4x128

    int b = blockIdx.x;
    int tid = threadIdx.x;
    int k = tid & 127;
    int h = tid >> 7;
    int j0 = h * 32;

    // weights into smem (coalesced copy, [j][k] layout preserved) — ONCE
    for (int idx = tid; idx < SS * SS; idx += 512) swt[idx] = g_RWN[idx];

    // per-thread coefficient registers — ONCE
    float wa1[32], wa2[32];
#pragma unroll
    for (int q = 0; q < 32; q++) {
        wa1[q] = g_RA1[k * SS + j0 + q];
        wa2[q] = g_RA2[k * SS + j0 + q];
    }

    float cmt = 0.f, vk = 0.f;
    if (h == 0) {
        cmt = g_cmt[k];
        vk = v0[b * SS + k];
        sv[k] = vk;
    }
    __syncthreads();

    const float4* sv4 = (const float4*)(sv + j0);    // 16B-aligned (j0 multiple of 32)
    size_t row = (size_t)b * TT_;

    for (int c = 0; c < NC; c++) {
        // wait for this chunk's wns/wds (usually already set -> single acquire load)
        if (tid == 0) {
            int* p = &g_prep_ready;
            int v;
            do {
                asm volatile("ld.acquire.gpu.global.s32 %0, [%1];" : "=r"(v) : "l"(p) : "memory");
                if (v >= c + 1) break;
                __nanosleep(200);
            } while (true);
        }
        __syncthreads();

#pragma unroll 1
        for (int t = 0; t < CHT; t++, row++) {
            float wns = 0.f, wds = 0.f;
            if (h == 0) {
                wns = g_wns[row * SS + k];
                wds = g_wds[row * SS + k];
            }
#pragma unroll 1
            for (int u = 0; u < 6; u++) {
                float num = 0.f, den = 0.f;
#pragma unroll
                for (int q4 = 0; q4 < 8; q4++) {
                    float4 vv = sv4[q4];                          // broadcast, 1 wavefront
                    int q = q4 * 4;
                    float w0 = swt[(j0 + q + 0) * SS + k];        // conflict-free LDS.32
                    float w1 = swt[(j0 + q + 1) * SS + k];
                    float w2 = swt[(j0 + q + 2) * SS + k];
                    float w3 = swt[(j0 + q + 3) * SS + k];
                    float t0h = tanh_fast(fmaf(vv.x, wa1[q + 0], wa2[q + 0]));
                    float t1h = tanh_fast(fmaf(vv.y, wa1[q + 1], wa2[q + 1]));
                    float t2h = tanh_fast(fmaf(vv.z, wa1[q + 2], wa2[q + 2]));
                    float t3h = tanh_fast(fmaf(vv.w, wa1[q + 3], wa2[q + 3]));
                    num = fmaf(w0, t0h, num); den = fmaf(fabsf(w0), t0h, den);
                    num = fmaf(w1, t1h, num); den = fmaf(fabsf(w1), t1h, den);
                    num = fmaf(w2, t2h, num); den = fmaf(fabsf(w2), t2h, den);
                    num = fmaf(w3, t3h, num); den = fmaf(fabsf(w3), t3h, den);
                }
                snum[h * SS + k] = num;
                sden[h * SS + k] = den;
                __syncthreads();
                if (h == 0) {
                    float nt = wns + snum[k] + snum[SS + k] + snum[2 * SS + k] + snum[3 * SS + k];
                    float dt = wds + sden[k] + sden[SS + k] + sden[2 * SS + k] + sden[3 * SS + k];
                    nt = fmaf(cmt, vk, nt);
                    vk = nt * __fdividef(1.f, dt);
                    sv[k] = vk;
                }
                __syncthreads();
            }
            if (h == 0) fused_out[row * SS + k] = vk;            // raw v; CG applied in post
        }

        // publish chunk completion (stores -> fence -> counter)
        __threadfence();
        __syncthreads();
        if (tid == 0) atomicAdd(&g_scan_ctr[c], 1);
    }
    if (h == 0) vfinal[b * SS + k] = vk;
}

// ---------------- post (chunked): fused = v * CG for chunk at t0 ----------------
__global__ void __launch_bounds__(256) post_kernel(float* __restrict__ fused, int t0)
{
    int b = blockIdx.y;
    size_t base = ((size_t)b * TT_ + t0) * SS / 4;
    size_t i = base + blockIdx.x * 256 + threadIdx.x;
    float4 f = ((float4*)fused)[i];
    float4 c = ((const float4*)g_CG)[i];
    f.x *= c.x; f.y *= c.y; f.z *= c.z; f.w *= c.w;
    ((float4*)fused)[i] = f;
}

// ---------------- streams/events (created at load, before harness checkpoints) ----------------
struct PipeRes {
    cudaStream_t s1;
    cudaEvent_t evFork, evJoin, evSens0;
    PipeRes() {
        cudaStreamCreateWithFlags(&s1, cudaStreamNonBlocking);
        cudaEventCreateWithFlags(&evFork, cudaEventDisableTiming);
        cudaEventCreateWithFlags(&evJoin, cudaEventDisableTiming);
        cudaEventCreateWithFlags(&evSens0, cudaEventDisableTiming);
    }
};
static PipeRes g_pipe;

// ---------------- launch ----------------
extern "C" void kernel_launch(void* const* d_in, const int* in_sizes, int n_in,
                              void* d_out, int out_size)
{
    const float* inputs    = (const float*)d_in[0];
    const float* ode_state = (const float*)d_in[1];
    const float* W_in      = (const float*)d_in[2];
    const float* b_in      = (const float*)d_in[3];
    const float* W_c       = (const float*)d_in[4];
    const float* b_c       = (const float*)d_in[5];
    const float* W_out     = (const float*)d_in[6];
    const float* b_out     = (const float*)d_in[7];
    const float* gleak     = (const float*)d_in[8];
    const float* vleak     = (const float*)d_in[9];
    const float* cm        = (const float*)d_in[10];
    const float* w         = (const float*)d_in[11];
    const float* sigma     = (const float*)d_in[12];
    const float* mu        = (const float*)d_in[13];
    const float* sw        = (const float*)d_in[14];
    const float* ssig      = (const float*)d_in[15];
    const float* smu       = (const float*)d_in[16];
    const float* erev      = (const float*)d_in[17];
    const float* serev     = (const float*)d_in[18];
    const float* mask      = (const float*)d_in[19];
    const float* smask     = (const float*)d_in[20];

    float* out      = (float*)d_out;                          // (B,T,M)
    float* vfinal   = out + (size_t)BB * TT_ * MM;            // (B,S)
    float* fusedout = vfinal + (size_t)BB * SS;               // (B,T,S)

    float *p_proj, *p_cg;
    cudaGetSymbolAddress((void**)&p_proj, g_proj);
    cudaGetSymbolAddress((void**)&p_cg, g_CG);

    cudaFuncSetAttribute(scan_kernel, cudaFuncAttributeMaxDynamicSharedMemorySize, SCAN_SMEM);

    cudaStream_t s0 = 0, s1 = g_pipe.s1;

    // ---- serial prologue on s0 ----
    reset_kernel<<<1, 32, 0, s0>>>();
    int prep_n = SS * SS + II * SS + SS;
    prep_kernel<<<(prep_n + 255) / 256, 256, 0, s0>>>(w, sigma, mu, erev, mask,
                                                      sw, ssig, smu, serev, smask,
                                                      gleak, vleak, cm);
    prep2_kernel<<<1, 128, 0, s0>>>();
    cudaEventRecord(g_pipe.evFork, s0);
    cudaStreamWaitEvent(s1, g_pipe.evFork, 0);

    // ---- preprocessing pipeline on s1 (chunked over T), flags after each chunk ----
    for (int c = 0; c < NC; c++) {
        int t0 = c * CHT;
        gemm_kernel<1, CHT><<<dim3(NPROJ / 64, BB), 256, 0, s1>>>(
            inputs, FF, W_in, NPROJ, b_in, p_proj, NPROJ, FF, t0);
        gemm_kernel<0, CHT><<<dim3(SS / 64, BB), 256, 0, s1>>>(
            p_proj, NPROJ, W_c, SS, b_c, p_cg, SS, II, t0);
        sensory_kernel<<<BB * (CHT / STT), 128, 0, s1>>>(t0);
        set_kernel<<<1, 32, 0, s1>>>(c);
        if (c == 0) cudaEventRecord(g_pipe.evSens0, s1);
    }
    // softmax over full T, folds sigmoid into CG in place
    softmax_cg_kernel<<<dim3(4, BB), 256, 0, s1>>>();

    // ---- persistent scan on s0 (starts after chunk 0 so chunk-0 preproc gets full chip)
    cudaStreamWaitEvent(s0, g_pipe.evSens0, 0);
    scan_kernel<<<BB, 512, SCAN_SMEM, s0>>>(ode_state, fusedout, vfinal);

    // ---- epilogue on s1, chunked, gated on scan progress via device flags ----
    for (int c = 0; c < NC; c++) {
        int t0 = c * CHT;
        gate_kernel<<<1, 32, 0, s1>>>(c);
        post_kernel<<<dim3(CHT * SS / (4 * 256), BB), 256, 0, s1>>>(fusedout, t0);
        gemm_kernel<0, CHT><<<dim3(MM / 64, BB), 256, 0, s1>>>(
            fusedout, SS, W_out, MM, b_out, out, MM, SS, t0);
    }
    // join: s0 (the measured stream) waits for the s1 epilogue
    cudaEventRecord(g_pipe.evJoin, s1);
    cudaStreamWaitEvent(s0, g_pipe.evJoin, 0);
}